// round 5
// baseline (speedup 1.0000x reference)
#include <cuda_runtime.h>
#include <math.h>
#include <stdint.h>

// ---------------------------------------------------------------------------
// Fused per-graph GNN: 5x TAGConv(K=2) + ReLU + gated softmax pooling.
// One CTA per graph (5000 CTAs, 256 threads). All features in shared memory.
//
// R5: tensor-core GEMM (3xTF32 m16n8k8) restructured for weight reuse:
//     each warp computes 2 m-tiles x half the n-tiles, so every B-fragment
//     LDG.128 feeds 6 MMAs (was 3). Warps 0-3: first ceil(NT/2) n-tiles,
//     warps 4-7: rest; both cover m-tile pairs {0,1},{2,3},{4,5},{6,7}.
// ---------------------------------------------------------------------------

#define NODES   100
#define EDGES   400
#define NTHR    256
#define ST      84      // smem row stride (floats): 84 mod 32 = 20 -> conflict-free A loads
#define MROWS   128     // 8 m-tiles * 16

typedef unsigned long long ull;

__device__ __forceinline__ uint32_t f2tf32(float f) {
    uint32_t u;
    asm("cvt.rna.tf32.f32 %0, %1;" : "=r"(u) : "f"(f));
    return u;
}

__device__ __forceinline__ void mma_tf32(float c[4], const uint32_t a[4],
                                         uint32_t b0, uint32_t b1) {
    asm("mma.sync.aligned.m16n8k8.row.col.f32.tf32.tf32.f32 "
        "{%0,%1,%2,%3}, {%4,%5,%6,%7}, {%8,%9}, {%0,%1,%2,%3};"
        : "+f"(c[0]), "+f"(c[1]), "+f"(c[2]), "+f"(c[3])
        : "r"(a[0]), "r"(a[1]), "r"(a[2]), "r"(a[3]), "r"(b0), "r"(b1));
}

// ---- packed hi/lo weights in B-fragment order (same layout as R4) ---------
// Layer l, pass p, ktile kt, ntile nt -> block of 128 floats:
//   lane*4 + {b0_hi, b1_hi, b0_lo, b1_lo}
// KT = {10,9,9,8,7}, NT = {9,9,8,7,5}; per-layer floats = 3*KT*NT*128
__device__ float g_Wpad[128256];

__global__ void prep_weights(const float* W0, const float* W1, const float* W2,
                             const float* W3, const float* W4) {
    const int DIN[5]  = {74, 70, 65, 60, 55};
    const int DOUT[5] = {70, 65, 60, 55, 37};
    const int KT[5]   = {10, 9, 9, 8, 7};
    const int NT[5]   = {9, 9, 8, 7, 5};
    const int OFF[6]  = {0, 34560, 65664, 93312, 114816, 128256};
    const float* Ws[5] = {W0, W1, W2, W3, W4};

    for (int idx = blockIdx.x * blockDim.x + threadIdx.x; idx < 128256;
         idx += gridDim.x * blockDim.x) {
        int l = 0;
        while (idx >= OFF[l + 1]) l++;
        int rel   = idx - OFF[l];
        int block = rel >> 7;
        int within = rel & 127;
        int lane = within >> 2;
        int j    = within & 3;          // 0:b0hi 1:b1hi 2:b0lo 3:b1lo
        int pnb  = KT[l] * NT[l];
        int p    = block / pnb;
        int r    = block - p * pnb;
        int kt   = r / NT[l];
        int nt   = r - kt * NT[l];
        int krow = (lane & 3) + ((j & 1) ? 4 : 0);
        int col  = nt * 8 + (lane >> 2);
        int k    = kt * 8 + krow;
        float w = 0.f;
        if (k < DIN[l] && col < DOUT[l])
            w = Ws[l][(p * DIN[l] + k) * DOUT[l] + col];
        uint32_t hi = f2tf32(w);
        float res;
        if (j < 2) {
            res = __uint_as_float(hi);
        } else {
            float lo = w - __uint_as_float(hi);
            res = __uint_as_float(f2tf32(lo));
        }
        g_Wpad[idx] = res;
    }
}

struct SmemLayout {
    float buf0[MROWS * ST];
    float buf1[MROWS * ST];
    float norm[128];
    float red[128];
    float gate[128];
    int   rowptr[104];
    int   cnt[128];
    unsigned short csr[EDGES];
};

// ---- propagation over padded width (pad cols zero in -> zero out) ---------
template <int DINP>
__device__ __forceinline__ void prop(const float* __restrict__ in,
                                     float* __restrict__ outb,
                                     const float* __restrict__ nrm,
                                     const int* __restrict__ rowptr,
                                     const unsigned short* __restrict__ csr,
                                     int tid) {
    constexpr int NQ = DINP / 4;
    for (int task = tid; task < NODES * NQ; task += NTHR) {
        int v  = task / NQ;
        int q  = task - v * NQ;
        int c0 = q * 4;
        float4 acc = make_float4(0.f, 0.f, 0.f, 0.f);
        int e0 = rowptr[v], e1 = rowptr[v + 1];
        for (int e = e0; e < e1; e++) {
            int s = csr[e];
            float f = nrm[s];
            float4 r = *reinterpret_cast<const float4*>(in + s * ST + c0);
            acc.x += f * r.x; acc.y += f * r.y;
            acc.z += f * r.z; acc.w += f * r.w;
        }
        float nv = nrm[v];
        acc.x *= nv; acc.y *= nv; acc.z *= nv; acc.w *= nv;
        *reinterpret_cast<float4*>(outb + v * ST + c0) = acc;
    }
}

// ---- GEMM pass: 2 m-tiles, n-tiles [NOFF, NOFF+NTH) -----------------------
// C layout: C[t][m][4]
template <int KT, int NT, int NOFF, int NTH>
__device__ __forceinline__ void gemm_mma(float (*C)[2][4],
                                         const float* __restrict__ H,
                                         const float* __restrict__ Wp,
                                         int mt0, int lane) {
    const float* hb = H + (mt0 * 16 + (lane >> 2)) * ST + (lane & 3);
    const float4* wbase = reinterpret_cast<const float4*>(Wp) + lane + NOFF * 32;
#pragma unroll
    for (int kt = 0; kt < KT; kt++) {
        uint32_t ahi[2][4], alo[2][4];
#pragma unroll
        for (int m = 0; m < 2; m++) {
            const float* hm = hb + m * (16 * ST) + kt * 8;
            float a0 = hm[0];
            float a1 = hm[8 * ST];
            float a2 = hm[4];
            float a3 = hm[4 + 8 * ST];
            ahi[m][0] = f2tf32(a0); ahi[m][1] = f2tf32(a1);
            ahi[m][2] = f2tf32(a2); ahi[m][3] = f2tf32(a3);
            alo[m][0] = f2tf32(a0 - __uint_as_float(ahi[m][0]));
            alo[m][1] = f2tf32(a1 - __uint_as_float(ahi[m][1]));
            alo[m][2] = f2tf32(a2 - __uint_as_float(ahi[m][2]));
            alo[m][3] = f2tf32(a3 - __uint_as_float(ahi[m][3]));
        }
        const float4* wrow = wbase + (size_t)kt * NT * 32;
#pragma unroll
        for (int t = 0; t < NTH; t++) {
            float4 w = __ldg(wrow + t * 32);
            uint32_t bh0 = __float_as_uint(w.x);
            uint32_t bh1 = __float_as_uint(w.y);
            uint32_t bl0 = __float_as_uint(w.z);
            uint32_t bl1 = __float_as_uint(w.w);
#pragma unroll
            for (int m = 0; m < 2; m++) {
                mma_tf32(C[t][m], ahi[m], bh0, bh1);
                mma_tf32(C[t][m], ahi[m], bl0, bl1);
                mma_tf32(C[t][m], alo[m], bh0, bh1);
            }
        }
    }
}

// ---- epilogue for one warp's n-range --------------------------------------
template <int NT, int NOFF, int NTH, int DOUT>
__device__ __forceinline__ void epilogue(float (*C)[2][4],
                                         float* __restrict__ bufOut,
                                         const float* __restrict__ B,
                                         int mt0, int lane) {
    int rbase = mt0 * 16 + (lane >> 2);
    int cb = 2 * (lane & 3);
#pragma unroll
    for (int t = 0; t < NTH; t++) {
        int c = (NOFF + t) * 8 + cb;
        float b0v = (c     < DOUT) ? __ldg(B + c)     : 0.f;
        float b1v = (c + 1 < DOUT) ? __ldg(B + c + 1) : 0.f;
#pragma unroll
        for (int m = 0; m < 2; m++) {
            int r0 = rbase + m * 16;
            float v0 = (c     < DOUT) ? fmaxf(C[t][m][0] + b0v, 0.f) : 0.f;
            float v1 = (c + 1 < DOUT) ? fmaxf(C[t][m][1] + b1v, 0.f) : 0.f;
            if (r0 < NODES)
                *reinterpret_cast<float2*>(bufOut + r0 * ST + c) =
                    make_float2(v0, v1);
            float v2 = (c     < DOUT) ? fmaxf(C[t][m][2] + b0v, 0.f) : 0.f;
            float v3 = (c + 1 < DOUT) ? fmaxf(C[t][m][3] + b1v, 0.f) : 0.f;
            if (r0 + 8 < NODES)
                *reinterpret_cast<float2*>(bufOut + (r0 + 8) * ST + c) =
                    make_float2(v2, v3);
        }
    }
}

// ---- one TAGConv layer ----------------------------------------------------
template <int KT, int NT, int DOUT>
__device__ __forceinline__ void layer(float* bufIn, float* bufOut,
                                      const float* __restrict__ Wp,
                                      const float* __restrict__ B,
                                      SmemLayout* sm, int tid) {
    constexpr int DINP   = KT * 8;
    constexpr int PSZ    = KT * NT * 128;
    constexpr int NTH_HI = NT - NT / 2;
    constexpr int NTH_LO = NT / 2;
    int wid  = tid >> 5;
    int lane = tid & 31;
    int mt0  = (wid & 3) * 2;
    bool hiHalf = (wid < 4);

    // U = A h -> bufOut
    prop<DINP>(bufIn, bufOut, sm->norm, sm->rowptr, sm->csr, tid);
    __syncthreads();

    float C[NTH_HI][2][4];
#pragma unroll
    for (int t = 0; t < NTH_HI; t++)
#pragma unroll
        for (int m = 0; m < 2; m++)
#pragma unroll
            for (int i = 0; i < 4; i++) C[t][m][i] = 0.f;

    if (hiHalf) {
        gemm_mma<KT, NT, 0, NTH_HI>(C, bufIn,  Wp,       mt0, lane);
        gemm_mma<KT, NT, 0, NTH_HI>(C, bufOut, Wp + PSZ, mt0, lane);
    } else {
        gemm_mma<KT, NT, NTH_HI, NTH_LO>(C, bufIn,  Wp,       mt0, lane);
        gemm_mma<KT, NT, NTH_HI, NTH_LO>(C, bufOut, Wp + PSZ, mt0, lane);
    }
    __syncthreads();

    // V = A U -> bufIn (h dead)
    prop<DINP>(bufOut, bufIn, sm->norm, sm->rowptr, sm->csr, tid);
    __syncthreads();

    if (hiHalf) {
        gemm_mma<KT, NT, 0, NTH_HI>(C, bufIn, Wp + 2 * PSZ, mt0, lane);
        epilogue<NT, 0, NTH_HI, DOUT>(C, bufOut, B, mt0, lane);
    } else {
        gemm_mma<KT, NT, NTH_HI, NTH_LO>(C, bufIn, Wp + 2 * PSZ, mt0, lane);
        epilogue<NT, NTH_HI, NTH_LO, DOUT>(C, bufOut, B, mt0, lane);
    }
    __syncthreads();
}

__global__ void __launch_bounds__(NTHR, 2)
gnn_fused_kernel(const float* __restrict__ x,
                 const int* __restrict__ src,
                 const int* __restrict__ dst,
                 const float* __restrict__ b0, const float* __restrict__ b1,
                 const float* __restrict__ b2, const float* __restrict__ b3,
                 const float* __restrict__ b4,
                 const float* __restrict__ gw, const float* __restrict__ gb,
                 float* __restrict__ out) {
    extern __shared__ char smem_raw[];
    SmemLayout* sm = reinterpret_cast<SmemLayout*>(smem_raw);
    const int tid = threadIdx.x;
    const int g   = blockIdx.x;

    float* A = sm->buf0;
    float* B = sm->buf1;

    // ---- zero both feature buffers (pad invariant), then load x
    {
        float4* z = reinterpret_cast<float4*>(sm->buf0);
        const int nq = 2 * MROWS * ST / 4;   // buf0+buf1 contiguous
        for (int i = tid; i < nq; i += NTHR)
            z[i] = make_float4(0.f, 0.f, 0.f, 0.f);
    }
    if (tid < 128) sm->cnt[tid] = 0;
    __syncthreads();
    {
        const float* xg = x + (size_t)g * (NODES * 74);
        for (int idx = tid; idx < NODES * 74; idx += NTHR) {
            int v = idx / 74;
            int c = idx - v * 74;
            A[v * ST + c] = xg[idx];
        }
    }

    // ---- per-graph CSR (by dst) + norm
    const int* srcg = src + g * EDGES;
    const int* dstg = dst + g * EDGES;
    const int base = g * NODES;
    for (int e = tid; e < EDGES; e += NTHR) {
        int dl = dstg[e] - base;
        atomicAdd(&sm->cnt[dl], 1);
    }
    __syncthreads();
    if (tid < NODES)
        sm->norm[tid] = rsqrtf(fmaxf((float)sm->cnt[tid], 1.f));
    for (int off = 1; off < 128; off <<= 1) {       // inclusive scan
        int t = 0;
        if (tid < 128 && tid >= off) t = sm->cnt[tid - off];
        __syncthreads();
        if (tid < 128 && tid >= off) sm->cnt[tid] += t;
        __syncthreads();
    }
    if (tid == 0) sm->rowptr[0] = 0;
    if (tid < NODES) sm->rowptr[tid + 1] = sm->cnt[tid];
    __syncthreads();
    if (tid < NODES) sm->cnt[tid] = sm->rowptr[tid];
    __syncthreads();
    for (int e = tid; e < EDGES; e += NTHR) {
        int sl = srcg[e] - base;
        int dl = dstg[e] - base;
        int pos = atomicAdd(&sm->cnt[dl], 1);
        sm->csr[pos] = (unsigned short)sl;
    }
    __syncthreads();

    // ---- 5 TAGConv layers       KT NT DOUT          Wpad offset
    layer<10, 9, 70>(A, B, g_Wpad +      0, b0, sm, tid);
    layer< 9, 9, 65>(B, A, g_Wpad +  34560, b1, sm, tid);
    layer< 9, 8, 60>(A, B, g_Wpad +  65664, b2, sm, tid);
    layer< 8, 7, 55>(B, A, g_Wpad +  93312, b3, sm, tid);
    layer< 7, 5, 37>(A, B, g_Wpad + 114816, b4, sm, tid);
    float* H = B;   // final features: 100 x 37 (cols 37..39 zero)

    // ---- gate = H @ gate_w + gate_b ; softmax over graph; pooled sum
    float gval = -1e30f;
    if (tid < NODES) {
        float s = __ldg(gb);
#pragma unroll
        for (int c = 0; c < 37; c++)
            s += H[tid * ST + c] * __ldg(gw + c);
        sm->gate[tid] = s;
        gval = s;
    }
    if (tid < 128) sm->red[tid] = gval;
    __syncthreads();
    for (int s = 64; s > 0; s >>= 1) {
        if (tid < s) sm->red[tid] = fmaxf(sm->red[tid], sm->red[tid + s]);
        __syncthreads();
    }
    float gmax = sm->red[0];
    __syncthreads();

    float ev = 0.f;
    if (tid < NODES) {
        ev = expf(sm->gate[tid] - gmax);
        sm->gate[tid] = ev;
    }
    if (tid < 128) sm->red[tid] = ev;
    __syncthreads();
    for (int s = 64; s > 0; s >>= 1) {
        if (tid < s) sm->red[tid] += sm->red[tid + s];
        __syncthreads();
    }
    float Z = sm->red[0];

    if (tid < 37) {
        float a = 0.f;
        for (int v = 0; v < NODES; v++)
            a += sm->gate[v] * H[v * ST + tid];
        out[g * 37 + tid] = a / Z;
    }
}

extern "C" void kernel_launch(void* const* d_in, const int* in_sizes, int n_in,
                              void* d_out, int out_size) {
    const float* x   = (const float*)d_in[0];
    const int*   src = (const int*)d_in[1];
    const int*   dst = (const int*)d_in[2];
    const float* W0 = (const float*)d_in[4];
    const float* b0 = (const float*)d_in[5];
    const float* W1 = (const float*)d_in[6];
    const float* b1 = (const float*)d_in[7];
    const float* W2 = (const float*)d_in[8];
    const float* b2 = (const float*)d_in[9];
    const float* W3 = (const float*)d_in[10];
    const float* b3 = (const float*)d_in[11];
    const float* W4 = (const float*)d_in[12];
    const float* b4 = (const float*)d_in[13];
    const float* gw = (const float*)d_in[14];
    const float* gb = (const float*)d_in[15];
    float* out = (float*)d_out;

    prep_weights<<<128, 256>>>(W0, W1, W2, W3, W4);

    const int smem_bytes = (int)sizeof(SmemLayout);
    cudaFuncSetAttribute(gnn_fused_kernel,
                         cudaFuncAttributeMaxDynamicSharedMemorySize,
                         smem_bytes);
    gnn_fused_kernel<<<5000, NTHR, smem_bytes>>>(
        x, src, dst,
        b0, b1, b2, b3, b4,
        gw, gb, out);
}